// round 1
// baseline (speedup 1.0000x reference)
#include <cuda_runtime.h>
#include <math.h>

#define EMB   64
#define NS    25
#define DEG   64
#define BATCH 4096
#define NSAMP (BATCH * NS)   // 102400

// Folded weights / scratch (static device globals: no allocation)
__device__ float g_A[2 * 64 * 128];         // [0]=prep∘w1x, [1]=prep∘w1n   layout [k][h]
__device__ float g_bias1[256];              // [b1x ; b1n]
__device__ float g_x0[128];                 // feats0 @ w1x.T (pre-relu)
__device__ float g_scr[(size_t)BATCH * 512]; // per batch: [h0cat(256, post-relu) ; h1mean(256)]

// ---------------------------------------------------------------------------
// Precompute A1x/A1n = prep_W.T @ w1{x,n}.T    (grid 64 x 128 threads)
// ---------------------------------------------------------------------------
__global__ void prep_A(const float* __restrict__ prep_W,
                       const float* __restrict__ w1x,
                       const float* __restrict__ w1n) {
    int idx = blockIdx.x * 128 + threadIdx.x;   // 0..8191
    int k = idx >> 7, h = idx & 127;
    float ax = 0.f, an = 0.f;
#pragma unroll
    for (int c = 0; c < 64; c++) {
        float p = prep_W[c * 64 + k];
        ax += p * w1x[h * 64 + c];
        an += p * w1n[h * 64 + c];
    }
    g_A[k * 128 + h]            = ax;
    g_A[64 * 128 + k * 128 + h] = an;
}

// ---------------------------------------------------------------------------
// Precompute x0 (h0 x-part, pre-relu) and folded biases  (1 block, 128 thr)
// ---------------------------------------------------------------------------
__global__ void prep_B(const float* __restrict__ emb,
                       const float* __restrict__ prep_W,
                       const float* __restrict__ prep_b,
                       const float* __restrict__ w1x,
                       const float* __restrict__ w1n,
                       int n_nodes) {
    __shared__ float f0[64];
    int t = threadIdx.x;
    if (t < 64) {
        const float* e = emb + (size_t)n_nodes * 64;
        float a = prep_b[t];
#pragma unroll
        for (int k = 0; k < 64; k++) a += e[k] * prep_W[t * 64 + k];
        f0[t] = a;
    }
    __syncthreads();
    float x0 = 0.f, bx = 0.f, bn = 0.f;
#pragma unroll
    for (int c = 0; c < 64; c++) {
        x0 += f0[c]     * w1x[t * 64 + c];
        bx += prep_b[c] * w1x[t * 64 + c];
        bn += prep_b[c] * w1n[t * 64 + c];
    }
    g_x0[t]          = x0;
    g_bias1[t]       = bx;
    g_bias1[128 + t] = bn;
}

// ---------------------------------------------------------------------------
// Main kernel: one block per batch id. 8 warps; each warp handles sample
// pairs. Gathers 26 embedding rows/sample, computes h1 = relu([e1@A1x ;
// mean2@A1n] + b), accumulates relu'd h1 and raw e1 for batch means.
// Shared: A (64KB) + 8*256 stage + reductions  (~75KB dynamic)
// ---------------------------------------------------------------------------
#define SMO_STAGE 16384
#define SMO_H1    (16384 + 2048)
#define SMO_F1    (SMO_H1 + 256)
#define SMO_P1    (SMO_F1 + 64)
#define SMEM_M_FLOATS (SMO_P1 + 32)

__global__ void __launch_bounds__(256)
main_kernel(const float* __restrict__ emb,
            const int* __restrict__ ids,
            const int* __restrict__ adj,
            const int* __restrict__ perm1,
            const int* __restrict__ perm2) {
    extern __shared__ float sm[];
    float* sA     = sm;
    float* sStage = sm + SMO_STAGE;
    float* sH1    = sm + SMO_H1;
    float* sF1    = sm + SMO_F1;
    int*   sP1    = (int*)(sm + SMO_P1);

    int t = threadIdx.x;
    int w = t >> 5, lane = t & 31;

    // Stage A1x|A1n into shared (16384 floats = 4096 float4)
    {
        const float4* src = (const float4*)g_A;
        float4* dst = (float4*)sA;
#pragma unroll
        for (int r = 0; r < 16; r++) dst[t + r * 256] = src[t + r * 256];
    }
    if (t < NS) sP1[t] = perm1[t];
    sH1[t] = 0.f;
    if (t < 64) sF1[t] = 0.f;
    __syncthreads();

    const int i   = blockIdx.x;
    const int id0 = __ldg(&ids[i]);
    const int p2  = __ldg(&perm2[lane < NS ? lane : 0]);

    const int   half  = lane >> 4;            // 0: x-part (A1x/e1), 1: n-part (A1n/mean2)
    const int   hc    = (lane & 15) * 8;      // column within half
    const int   obase = lane * 8;             // absolute output index base (0..248)
    const float* Abase = sA + (half * 64) * 128 + hc;
    const int   eoff  = half * 64;
    float* st = sStage + w * 256;

    float breg[8];
#pragma unroll
    for (int q = 0; q < 8; q++) breg[q] = g_bias1[obase + q];

    float hacc[8] = {0, 0, 0, 0, 0, 0, 0, 0};
    float f1x = 0.f, f1y = 0.f;
    const float inv25 = 1.0f / 25.0f;

    for (int s0 = 2 * w; s0 < NS; s0 += 16) {
        const int sa = s0, sb = s0 + 1;
        const bool vb = (sb < NS);
        const int id1a = __ldg(&adj[(size_t)id0 * DEG + sP1[sa]]);
        const int id1b = vb ? __ldg(&adj[(size_t)id0 * DEG + sP1[sb]]) : id1a;

        float2 e1a = *(const float2*)(emb + (size_t)id1a * 64 + 2 * lane);
        float2 e1b = *(const float2*)(emb + (size_t)id1b * 64 + 2 * lane);
        int nba = __ldg(&adj[(size_t)id1a * DEG + p2]);   // lanes 0..24 hold hop-2 ids
        int nbb = __ldg(&adj[(size_t)id1b * DEG + p2]);

        float2 suma = make_float2(0.f, 0.f), sumb = make_float2(0.f, 0.f);
#pragma unroll 5
        for (int k = 0; k < NS; k++) {
            int ia = __shfl_sync(0xffffffffu, nba, k);
            int ib = __shfl_sync(0xffffffffu, nbb, k);
            float2 va  = *(const float2*)(emb + (size_t)ia * 64 + 2 * lane);
            float2 vb2 = *(const float2*)(emb + (size_t)ib * 64 + 2 * lane);
            suma.x += va.x;  suma.y += va.y;
            sumb.x += vb2.x; sumb.y += vb2.y;
        }

        // stage [e1a | mean2a | e1b | mean2b]
        st[2 * lane]           = e1a.x;         st[2 * lane + 1]       = e1a.y;
        st[64 + 2 * lane]      = suma.x * inv25; st[64 + 2 * lane + 1] = suma.y * inv25;
        st[128 + 2 * lane]     = e1b.x;         st[128 + 2 * lane + 1] = e1b.y;
        st[192 + 2 * lane]     = sumb.x * inv25; st[192 + 2 * lane + 1] = sumb.y * inv25;
        f1x += e1a.x + (vb ? e1b.x : 0.f);
        f1y += e1a.y + (vb ? e1b.y : 0.f);
        __syncwarp();

        float acc[16];
#pragma unroll
        for (int q = 0; q < 16; q++) acc[q] = 0.f;
#pragma unroll 8
        for (int k = 0; k < 64; k++) {
            float ea = st[eoff + k];
            float eb = st[128 + eoff + k];
            float4 A0 = *(const float4*)(Abase + k * 128);
            float4 A1 = *(const float4*)(Abase + k * 128 + 4);
            acc[0]  += ea * A0.x; acc[1]  += ea * A0.y; acc[2]  += ea * A0.z; acc[3]  += ea * A0.w;
            acc[4]  += ea * A1.x; acc[5]  += ea * A1.y; acc[6]  += ea * A1.z; acc[7]  += ea * A1.w;
            acc[8]  += eb * A0.x; acc[9]  += eb * A0.y; acc[10] += eb * A0.z; acc[11] += eb * A0.w;
            acc[12] += eb * A1.x; acc[13] += eb * A1.y; acc[14] += eb * A1.z; acc[15] += eb * A1.w;
        }
#pragma unroll
        for (int q = 0; q < 8; q++) {
            hacc[q] += fmaxf(acc[q] + breg[q], 0.f);
            if (vb) hacc[q] += fmaxf(acc[8 + q] + breg[q], 0.f);
        }
        __syncwarp();
    }

    // flush per-warp partials
#pragma unroll
    for (int q = 0; q < 8; q++) atomicAdd(&sH1[obase + q], hacc[q]);
    atomicAdd(&sF1[2 * lane],     f1x);
    atomicAdd(&sF1[2 * lane + 1], f1y);
    __syncthreads();

    // tail: h0 (relu) and h1mean -> scratch
    float* scr = g_scr + (size_t)i * 512;
    if (t < 128) {
        float a = 0.f;
        const float* An = sA + 64 * 128 + t;   // A1n[k][t]
#pragma unroll 8
        for (int k = 0; k < 64; k++) a += sF1[k] * An[k * 128];
        a = a * inv25 + g_bias1[128 + t];
        scr[t]       = fmaxf(g_x0[t], 0.f);
        scr[128 + t] = fmaxf(a, 0.f);
    }
    scr[256 + t] = sH1[t] * inv25;
}

// ---------------------------------------------------------------------------
// Final: batched layer-2 matvecs (16 rows/block) + L2-normalize + fc
// ---------------------------------------------------------------------------
__global__ void __launch_bounds__(256)
final_kernel(const float* __restrict__ w2x,
             const float* __restrict__ w2n,
             const float* __restrict__ fcW,
             const float* __restrict__ fcb,
             float* __restrict__ out) {
    __shared__ float in_sh[16][512];
    __shared__ float sSq[16], sDot[16];
    int t  = threadIdx.x;
    int r0 = blockIdx.x * 16;

    {
        const float4* src = (const float4*)(g_scr + (size_t)r0 * 512);
        float4* dst = (float4*)&in_sh[0][0];
#pragma unroll
        for (int q = 0; q < 8; q++) dst[t + q * 256] = src[t + q * 256];
    }
    if (t < 16) { sSq[t] = 0.f; sDot[t] = 0.f; }
    __syncthreads();

    const float* W  = (t < 128) ? (w2x + (size_t)t * 256) : (w2n + (size_t)(t - 128) * 256);
    const int  ioff = (t < 128) ? 0 : 256;   // h0cat vs h1mean
    float acc[16];
#pragma unroll
    for (int r = 0; r < 16; r++) acc[r] = 0.f;

    for (int c = 0; c < 256; c += 4) {
        float4 wv = *(const float4*)(W + c);
#pragma unroll
        for (int r = 0; r < 16; r++) {
            float4 x = *(const float4*)&in_sh[r][ioff + c];
            acc[r] += x.x * wv.x + x.y * wv.y + x.z * wv.z + x.w * wv.w;
        }
    }

    float fw = fcW[t];
#pragma unroll
    for (int r = 0; r < 16; r++) {
        float v  = acc[r];
        float sq = v * v;
        float dt = v * fw;
#pragma unroll
        for (int o = 16; o > 0; o >>= 1) {
            sq += __shfl_xor_sync(0xffffffffu, sq, o);
            dt += __shfl_xor_sync(0xffffffffu, dt, o);
        }
        if ((t & 31) == 0) { atomicAdd(&sSq[r], sq); atomicAdd(&sDot[r], dt); }
    }
    __syncthreads();
    if (t < 16) {
        float nrm = sqrtf(sSq[t]);
        out[r0 + t] = sDot[t] / fmaxf(nrm, 1e-12f) + fcb[0];
    }
}

// ---------------------------------------------------------------------------
extern "C" void kernel_launch(void* const* d_in, const int* in_sizes, int n_in,
                              void* d_out, int out_size) {
    const float* embedding = (const float*)d_in[0];
    const float* prep_W    = (const float*)d_in[1];
    const float* prep_b    = (const float*)d_in[2];
    const float* w1x       = (const float*)d_in[3];
    const float* w1n       = (const float*)d_in[4];
    const float* w2x       = (const float*)d_in[5];
    const float* w2n       = (const float*)d_in[6];
    const float* fcW       = (const float*)d_in[7];
    const float* fcb       = (const float*)d_in[8];
    const int*   ids       = (const int*)d_in[9];
    const int*   adj       = (const int*)d_in[10];
    const int*   perm1     = (const int*)d_in[11];
    const int*   perm2     = (const int*)d_in[12];
    const int n_nodes = in_sizes[0] / EMB - 1;

    prep_A<<<64, 128>>>(prep_W, w1x, w1n);
    prep_B<<<1, 128>>>(embedding, prep_W, prep_b, w1x, w1n, n_nodes);

    const int smem_m = SMEM_M_FLOATS * (int)sizeof(float);
    cudaFuncSetAttribute(main_kernel, cudaFuncAttributeMaxDynamicSharedMemorySize, smem_m);
    main_kernel<<<BATCH, 256, smem_m>>>(embedding, ids, adj, perm1, perm2);

    final_kernel<<<BATCH / 16, 256>>>(w2x, w2n, fcW, fcb, (float*)d_out);
}

// round 2
// speedup vs baseline: 1.4854x; 1.4854x over previous
#include <cuda_runtime.h>
#include <math.h>

#define EMB   64
#define NS    25
#define DEG   64
#define BATCH 4096
#define NSAMP (BATCH * NS)   // 102400

typedef unsigned long long ull;

// fma.rn.f32x2 — packed fp32 FMA (Blackwell). acc += a*b (two lanes)
#define FFMA2(acc, a, b) \
    asm("fma.rn.f32x2 %0, %1, %2, %3;" : "=l"(acc) : "l"(a), "l"(b), "l"(acc))

// ---------------- static device scratch (no allocation) --------------------
__device__ float g_At[256 * 64];              // A transposed: [c][k]; c<128 -> A1x, c>=128 -> A1n
__device__ float g_bias1[256];                // [b1x ; b1n]
__device__ float g_x0[128];                   // feats0 @ w1x.T (pre-relu)
__device__ float g_feats[(size_t)NSAMP * 128];// per sample: [e1(64) | mean2(64)]
__device__ float g_scr[(size_t)BATCH * 512];  // per batch: [h0x;h0n;h1mean(256)]

// ---------------------------------------------------------------------------
// prep_A: A1x/A1n = prep_W.T @ w1{x,n}.T, stored transposed [c][k]
// ---------------------------------------------------------------------------
__global__ void prep_A(const float* __restrict__ prep_W,
                       const float* __restrict__ w1x,
                       const float* __restrict__ w1n) {
    int idx = blockIdx.x * 128 + threadIdx.x;   // 0..8191
    int k = idx >> 7, h = idx & 127;
    float ax = 0.f, an = 0.f;
#pragma unroll
    for (int c = 0; c < 64; c++) {
        float p = prep_W[c * 64 + k];
        ax += p * w1x[h * 64 + c];
        an += p * w1n[h * 64 + c];
    }
    g_At[h * 64 + k]           = ax;
    g_At[(128 + h) * 64 + k]   = an;
}

// ---------------------------------------------------------------------------
// prep_B: x0 (h0 x-part, pre-relu) + folded biases   (1 block, 128 thr)
// ---------------------------------------------------------------------------
__global__ void prep_B(const float* __restrict__ emb,
                       const float* __restrict__ prep_W,
                       const float* __restrict__ prep_b,
                       const float* __restrict__ w1x,
                       const float* __restrict__ w1n,
                       int n_nodes) {
    __shared__ float f0[64];
    int t = threadIdx.x;
    if (t < 64) {
        const float* e = emb + (size_t)n_nodes * 64;
        float a = prep_b[t];
#pragma unroll
        for (int k = 0; k < 64; k++) a += e[k] * prep_W[t * 64 + k];
        f0[t] = a;
    }
    __syncthreads();
    float x0 = 0.f, bx = 0.f, bn = 0.f;
#pragma unroll
    for (int c = 0; c < 64; c++) {
        x0 += f0[c]     * w1x[t * 64 + c];
        bx += prep_b[c] * w1x[t * 64 + c];
        bn += prep_b[c] * w1n[t * 64 + c];
    }
    g_x0[t]          = x0;
    g_bias1[t]       = bx;
    g_bias1[128 + t] = bn;
}

// ---------------------------------------------------------------------------
// gather_kernel: 1 warp = 1 sample. Stages [e1 | mean2raw] to g_feats.
// 26 independent 256B row gathers per warp -> deep MLP, LTS-bound.
// ---------------------------------------------------------------------------
__global__ void __launch_bounds__(256)
gather_kernel(const float* __restrict__ emb,
              const int* __restrict__ ids,
              const int* __restrict__ adj,
              const int* __restrict__ perm1,
              const int* __restrict__ perm2) {
    int t = threadIdx.x;
    int w = t >> 5, lane = t & 31;
    int s = blockIdx.x * 8 + w;                  // sample index 0..102399
    int i = s / NS;
    int j = s - i * NS;

    int id0 = __ldg(&ids[i]);
    int p1  = __ldg(&perm1[j]);
    int id1 = __ldg(&adj[(size_t)id0 * DEG + p1]);

    int p2  = __ldg(&perm2[lane < NS ? lane : 0]);
    int nb  = __ldg(&adj[(size_t)id1 * DEG + p2]);

    float2 e1 = *(const float2*)(emb + (size_t)id1 * 64 + 2 * lane);

    float sx = 0.f, sy = 0.f;
#pragma unroll
    for (int k = 0; k < NS; k++) {
        int idk = __shfl_sync(0xffffffffu, nb, k);
        float2 v = *(const float2*)(emb + (size_t)idk * 64 + 2 * lane);
        sx += v.x; sy += v.y;
    }
    const float inv25 = 1.0f / 25.0f;
    float* dst = g_feats + (size_t)s * 128;
    *(float2*)(dst + 2 * lane)      = e1;
    *(float2*)(dst + 64 + 2 * lane) = make_float2(sx * inv25, sy * inv25);
}

// ---------------------------------------------------------------------------
// compute_kernel: 1 block per batch id. Thread c owns output column c.
// h1[s][c] = relu(feat_s . A[:,c] + b[c]); group-mean over 25 -> scratch.
// A transposed in shared (row stride 68 floats, conflict-light, amortized
// over 25 samples). FFMA2 packed fp32.
// ---------------------------------------------------------------------------
#define SM_A_FL    (256 * 68)                 // 17408
#define SM_F_FL    (NS * 128)                 // 3200
#define SM_C_FLOATS (SM_A_FL + SM_F_FL + 64)

__global__ void __launch_bounds__(256)
compute_kernel() {
    extern __shared__ float sm[];
    float* sA    = sm;                        // [256][68]
    float* sF    = sm + SM_A_FL;              // [25][128]
    float* sMean = sm + SM_A_FL + SM_F_FL;    // [64]

    int t = threadIdx.x;
    const int i = blockIdx.x;

    // stage A (transpose already done; insert 68-stride padding)
    {
        const float4* src = (const float4*)g_At;
#pragma unroll
        for (int r = 0; r < 16; r++) {
            int i4 = t + r * 256;             // 0..4095 float4s
            int c  = i4 >> 4;
            int kq = i4 & 15;
            *(float4*)(sA + c * 68 + kq * 4) = src[i4];
        }
    }
    // stage feats for this batch (25 x 128 floats, contiguous)
    {
        const float4* src = (const float4*)(g_feats + (size_t)i * NS * 128);
        float4* dst = (float4*)sF;
#pragma unroll
        for (int r = 0; r < 4; r++) {
            int idx = t + r * 256;
            if (idx < 800) dst[idx] = src[idx];
        }
    }
    __syncthreads();

    const int c = t;
    const int kbase = (c < 128) ? 0 : 64;     // e1-part vs mean2-part
    const float* Ac = sA + c * 68;
    const float* fb = sF + kbase;

    ull acc[NS];
#pragma unroll
    for (int s = 0; s < NS; s++) acc[s] = 0ull;

    for (int k4 = 0; k4 < 16; k4++) {
        ulonglong2 a2 = *(const ulonglong2*)(Ac + k4 * 4);
#pragma unroll
        for (int s = 0; s < NS; s++) {
            ulonglong2 f2 = *(const ulonglong2*)(fb + s * 128 + k4 * 4);
            FFMA2(acc[s], f2.x, a2.x);
            FFMA2(acc[s], f2.y, a2.y);
        }
    }

    const float b = g_bias1[c];
    const float inv25 = 1.0f / 25.0f;
    float hsum = 0.f;
#pragma unroll
    for (int s = 0; s < NS; s++) {
        float lo = __uint_as_float((unsigned)acc[s]);
        float hi = __uint_as_float((unsigned)(acc[s] >> 32));
        hsum += fmaxf(lo + hi + b, 0.f);
    }

    // mean1 (mean of e1 over 25 samples) for h0's neighbor branch
    if (t < 64) {
        float m = 0.f;
#pragma unroll
        for (int s = 0; s < NS; s++) m += sF[s * 128 + t];
        sMean[t] = m * inv25;
    }
    __syncthreads();

    float* scr = g_scr + (size_t)i * 512;
    if (t < 128) {
        scr[t] = fmaxf(g_x0[t], 0.f);         // h0 x-part (constant, pre-relu'd x0)
    } else {
        float a = 0.f;                        // h0 n-part: mean1 @ A1n  (this thread's column)
#pragma unroll
        for (int k4 = 0; k4 < 16; k4++) {
            float4 av = *(const float4*)(Ac + k4 * 4);
            a += av.x * sMean[k4 * 4] + av.y * sMean[k4 * 4 + 1]
               + av.z * sMean[k4 * 4 + 2] + av.w * sMean[k4 * 4 + 3];
        }
        scr[t] = fmaxf(a + b, 0.f);
    }
    scr[256 + t] = hsum * inv25;
}

// ---------------------------------------------------------------------------
// final_kernel: layer-2 matvecs (16 rows/block) + L2-normalize + fc, FFMA2
// ---------------------------------------------------------------------------
__global__ void __launch_bounds__(256)
final_kernel(const float* __restrict__ w2x,
             const float* __restrict__ w2n,
             const float* __restrict__ fcW,
             const float* __restrict__ fcb,
             float* __restrict__ out) {
    __shared__ float in_sh[16][512];
    __shared__ float sSq[16], sDot[16];
    int t  = threadIdx.x;
    int r0 = blockIdx.x * 16;

    {
        const float4* src = (const float4*)(g_scr + (size_t)r0 * 512);
        float4* dst = (float4*)&in_sh[0][0];
#pragma unroll
        for (int q = 0; q < 8; q++) dst[t + q * 256] = src[t + q * 256];
    }
    if (t < 16) { sSq[t] = 0.f; sDot[t] = 0.f; }
    __syncthreads();

    const float* W  = (t < 128) ? (w2x + (size_t)t * 256) : (w2n + (size_t)(t - 128) * 256);
    const int  ioff = (t < 128) ? 0 : 256;   // h0cat vs h1mean
    ull acc[16];
#pragma unroll
    for (int r = 0; r < 16; r++) acc[r] = 0ull;

    for (int c = 0; c < 256; c += 4) {
        ulonglong2 wv = *(const ulonglong2*)(W + c);
#pragma unroll
        for (int r = 0; r < 16; r++) {
            ulonglong2 x = *(const ulonglong2*)&in_sh[r][ioff + c];
            FFMA2(acc[r], x.x, wv.x);
            FFMA2(acc[r], x.y, wv.y);
        }
    }

    float fw = fcW[t];
#pragma unroll
    for (int r = 0; r < 16; r++) {
        float v  = __uint_as_float((unsigned)acc[r])
                 + __uint_as_float((unsigned)(acc[r] >> 32));
        float sq = v * v;
        float dt = v * fw;
#pragma unroll
        for (int o = 16; o > 0; o >>= 1) {
            sq += __shfl_xor_sync(0xffffffffu, sq, o);
            dt += __shfl_xor_sync(0xffffffffu, dt, o);
        }
        if ((t & 31) == 0) { atomicAdd(&sSq[r], sq); atomicAdd(&sDot[r], dt); }
    }
    __syncthreads();
    if (t < 16) {
        float nrm = sqrtf(sSq[t]);
        out[r0 + t] = sDot[t] / fmaxf(nrm, 1e-12f) + fcb[0];
    }
}

// ---------------------------------------------------------------------------
extern "C" void kernel_launch(void* const* d_in, const int* in_sizes, int n_in,
                              void* d_out, int out_size) {
    const float* embedding = (const float*)d_in[0];
    const float* prep_W    = (const float*)d_in[1];
    const float* prep_b    = (const float*)d_in[2];
    const float* w1x       = (const float*)d_in[3];
    const float* w1n       = (const float*)d_in[4];
    const float* w2x       = (const float*)d_in[5];
    const float* w2n       = (const float*)d_in[6];
    const float* fcW       = (const float*)d_in[7];
    const float* fcb       = (const float*)d_in[8];
    const int*   ids       = (const int*)d_in[9];
    const int*   adj       = (const int*)d_in[10];
    const int*   perm1     = (const int*)d_in[11];
    const int*   perm2     = (const int*)d_in[12];
    const int n_nodes = in_sizes[0] / EMB - 1;

    prep_A<<<64, 128>>>(prep_W, w1x, w1n);
    prep_B<<<1, 128>>>(embedding, prep_W, prep_b, w1x, w1n, n_nodes);

    gather_kernel<<<NSAMP / 8, 256>>>(embedding, ids, adj, perm1, perm2);

    const int smem_c = SM_C_FLOATS * (int)sizeof(float);
    cudaFuncSetAttribute(compute_kernel, cudaFuncAttributeMaxDynamicSharedMemorySize, smem_c);
    compute_kernel<<<BATCH, 256, smem_c>>>();

    final_kernel<<<BATCH / 16, 256>>>(w2x, w2n, fcW, fcb, (float*)d_out);
}

// round 3
// speedup vs baseline: 1.6216x; 1.0917x over previous
#include <cuda_runtime.h>
#include <math.h>

#define EMB   64
#define NS    25
#define DEG   64
#define BATCH 4096
#define NSAMP (BATCH * NS)   // 102400

typedef unsigned long long ull;

// fma.rn.f32x2 — packed fp32 FMA (Blackwell). acc += a*b (two lanes)
#define FFMA2(acc, a, b) \
    asm("fma.rn.f32x2 %0, %1, %2, %3;" : "=l"(acc) : "l"(a), "l"(b), "l"(acc))

// A layout: [64 colgroups][16 k4][4 cols][4 k], group stride 260 floats
#define A_GS 260
#define A_FLOATS (64 * A_GS)    // 16640

// ---------------- static device scratch (no allocation) --------------------
__device__ float g_At[A_FLOATS];              // folded layer-1 weights, blocked layout
__device__ float g_bias1[256];                // [b1x ; b1n]
__device__ float g_x0[128];                   // feats0 @ w1x.T (pre-relu)
__device__ float g_feats[(size_t)NSAMP * 128];// per sample: [e1(64) | mean2(64)]
__device__ float g_scr[(size_t)BATCH * 512];  // per batch: [h0x;h0n;h1mean(256)]

// ---------------------------------------------------------------------------
// prep_A: A1x/A1n = prep_W.T @ w1{x,n}.T, stored in blocked layout
// ---------------------------------------------------------------------------
__global__ void prep_A(const float* __restrict__ prep_W,
                       const float* __restrict__ w1x,
                       const float* __restrict__ w1n) {
    int idx = blockIdx.x * 128 + threadIdx.x;   // 0..8191
    int k = idx >> 7, h = idx & 127;
    float ax = 0.f, an = 0.f;
#pragma unroll
    for (int c = 0; c < 64; c++) {
        float p = prep_W[c * 64 + k];
        ax += p * w1x[h * 64 + c];
        an += p * w1n[h * 64 + c];
    }
    int cx = h, cn = 128 + h;
    g_At[(cx >> 2) * A_GS + (k >> 2) * 16 + (cx & 3) * 4 + (k & 3)] = ax;
    g_At[(cn >> 2) * A_GS + (k >> 2) * 16 + (cn & 3) * 4 + (k & 3)] = an;
}

// ---------------------------------------------------------------------------
// prep_B: x0 (h0 x-part, pre-relu) + folded biases   (1 block, 128 thr)
// ---------------------------------------------------------------------------
__global__ void prep_B(const float* __restrict__ emb,
                       const float* __restrict__ prep_W,
                       const float* __restrict__ prep_b,
                       const float* __restrict__ w1x,
                       const float* __restrict__ w1n,
                       int n_nodes) {
    __shared__ float f0[64];
    int t = threadIdx.x;
    if (t < 64) {
        const float* e = emb + (size_t)n_nodes * 64;
        float a = prep_b[t];
#pragma unroll
        for (int k = 0; k < 64; k++) a += e[k] * prep_W[t * 64 + k];
        f0[t] = a;
    }
    __syncthreads();
    float x0 = 0.f, bx = 0.f, bn = 0.f;
#pragma unroll
    for (int c = 0; c < 64; c++) {
        x0 += f0[c]     * w1x[t * 64 + c];
        bx += prep_b[c] * w1x[t * 64 + c];
        bn += prep_b[c] * w1n[t * 64 + c];
    }
    g_x0[t]          = x0;
    g_bias1[t]       = bx;
    g_bias1[128 + t] = bn;
}

// ---------------------------------------------------------------------------
// gather_kernel: 1 warp = 1 sample. Stages [e1 | mean2] to g_feats.
// ---------------------------------------------------------------------------
__global__ void __launch_bounds__(256)
gather_kernel(const float* __restrict__ emb,
              const int* __restrict__ ids,
              const int* __restrict__ adj,
              const int* __restrict__ perm1,
              const int* __restrict__ perm2) {
    int t = threadIdx.x;
    int w = t >> 5, lane = t & 31;
    int s = blockIdx.x * 8 + w;                  // sample index 0..102399
    int i = s / NS;
    int j = s - i * NS;

    int id0 = __ldg(&ids[i]);
    int p1  = __ldg(&perm1[j]);
    int id1 = __ldg(&adj[(size_t)id0 * DEG + p1]);

    int p2  = __ldg(&perm2[lane < NS ? lane : 0]);
    int nb  = __ldg(&adj[(size_t)id1 * DEG + p2]);

    float2 e1 = *(const float2*)(emb + (size_t)id1 * 64 + 2 * lane);

    float sx = 0.f, sy = 0.f;
#pragma unroll
    for (int k = 0; k < NS; k++) {
        int idk = __shfl_sync(0xffffffffu, nb, k);
        float2 v = *(const float2*)(emb + (size_t)idk * 64 + 2 * lane);
        sx += v.x; sy += v.y;
    }
    const float inv25 = 1.0f / 25.0f;
    float* dst = g_feats + (size_t)s * 128;
    *(float2*)(dst + 2 * lane)      = e1;
    *(float2*)(dst + 64 + 2 * lane) = make_float2(sx * inv25, sy * inv25);
}

// ---------------------------------------------------------------------------
// compute_kernel: 1 block = 2 batch ids (A staged once). Thread owns 4
// adjacent output columns x ~7 samples. Conflict-free A loads, FFMA2-dense.
// smem: A 16640 + sF 3200 + sH1 256 + sMean 64 + sBias 256 = 20416 floats
// ---------------------------------------------------------------------------
#define SMO_F   A_FLOATS
#define SMO_H1  (SMO_F + NS * 128)
#define SMO_MN  (SMO_H1 + 256)
#define SMO_B   (SMO_MN + 64)
#define SM_C_FLOATS (SMO_B + 256)

__global__ void __launch_bounds__(256)
compute_kernel() {
    extern __shared__ float sm[];
    float* sA    = sm;
    float* sF    = sm + SMO_F;
    float* sH1   = sm + SMO_H1;
    float* sMean = sm + SMO_MN;
    float* sBias = sm + SMO_B;

    int t = threadIdx.x;

    // stage A (blocked layout, linear copy) + biases
    {
        const float4* src = (const float4*)g_At;
        float4* dst = (float4*)sA;
#pragma unroll
        for (int r = 0; r < 17; r++) {
            int idx = t + r * 256;
            if (idx < A_FLOATS / 4) dst[idx] = src[idx];
        }
        sBias[t] = g_bias1[t];
    }

    const int cg = t & 63;            // column group -> cols c0..c0+3
    const int sg = t >> 6;            // sample subset: s = sg + 4m
    const int c0 = cg * 4;
    const int kbase = (cg < 32) ? 0 : 64;   // e1-part vs mean2-part
    const float* Ab = sA + cg * A_GS;
    const float inv25 = 1.0f / 25.0f;

    for (int b = 0; b < 2; b++) {
        const int i = blockIdx.x * 2 + b;
        __syncthreads();              // A staged / prev iter done
        sH1[t] = 0.f;
        {
            const float4* fsrc = (const float4*)(g_feats + (size_t)i * NS * 128);
            float4* fdst = (float4*)sF;
#pragma unroll
            for (int r = 0; r < 4; r++) {
                int idx = t + r * 256;
                if (idx < NS * 32) fdst[idx] = fsrc[idx];
            }
        }
        __syncthreads();

        ull acc[7][4];
#pragma unroll
        for (int m = 0; m < 7; m++)
#pragma unroll
            for (int j = 0; j < 4; j++) acc[m][j] = 0ull;

#pragma unroll
        for (int k4 = 0; k4 < 16; k4++) {
            ulonglong2 a0 = *(const ulonglong2*)(Ab + k4 * 16);
            ulonglong2 a1 = *(const ulonglong2*)(Ab + k4 * 16 + 4);
            ulonglong2 a2 = *(const ulonglong2*)(Ab + k4 * 16 + 8);
            ulonglong2 a3 = *(const ulonglong2*)(Ab + k4 * 16 + 12);
#pragma unroll
            for (int m = 0; m < 7; m++) {
                int s = sg + 4 * m;
                if (s < NS) {
                    ulonglong2 f2 = *(const ulonglong2*)(sF + s * 128 + kbase + k4 * 4);
                    FFMA2(acc[m][0], f2.x, a0.x); FFMA2(acc[m][0], f2.y, a0.y);
                    FFMA2(acc[m][1], f2.x, a1.x); FFMA2(acc[m][1], f2.y, a1.y);
                    FFMA2(acc[m][2], f2.x, a2.x); FFMA2(acc[m][2], f2.y, a2.y);
                    FFMA2(acc[m][3], f2.x, a3.x); FFMA2(acc[m][3], f2.y, a3.y);
                }
            }
        }

        // relu + partial sums over this thread's samples
        float hs[4] = {0.f, 0.f, 0.f, 0.f};
#pragma unroll
        for (int m = 0; m < 7; m++) {
            int s = sg + 4 * m;
            if (s < NS) {
#pragma unroll
                for (int j = 0; j < 4; j++) {
                    float lo = __uint_as_float((unsigned)acc[m][j]);
                    float hi = __uint_as_float((unsigned)(acc[m][j] >> 32));
                    hs[j] += fmaxf(lo + hi + sBias[c0 + j], 0.f);
                }
            }
        }
#pragma unroll
        for (int j = 0; j < 4; j++) atomicAdd(&sH1[c0 + j], hs[j]);

        // mean of e1 over 25 samples (for h0 neighbor branch)
        if (t < 64) {
            float m = 0.f;
#pragma unroll
            for (int s = 0; s < NS; s++) m += sF[s * 128 + t];
            sMean[t] = m * inv25;
        }
        __syncthreads();

        float* scr = g_scr + (size_t)i * 512;
        if (t < 128) {
            scr[t] = fmaxf(g_x0[t], 0.f);
        } else {
            // h0 n-part: mean1 . A1n[:,t]
            int cgc = t >> 2, jc = t & 3;
            const float* Ac = sA + cgc * A_GS + jc * 4;
            float a = 0.f;
#pragma unroll
            for (int k4 = 0; k4 < 16; k4++) {
                float4 av = *(const float4*)(Ac + k4 * 16);
                float4 mv = *(const float4*)(sMean + k4 * 4);
                a += av.x * mv.x + av.y * mv.y + av.z * mv.z + av.w * mv.w;
            }
            scr[t] = fmaxf(a + sBias[t], 0.f);
        }
        scr[256 + t] = sH1[t] * inv25;
    }
}

// ---------------------------------------------------------------------------
// final_kernel: layer-2 matvecs (16 rows/block), thread = 2 cols x 8 rows,
// then L2-normalize + fc.
// ---------------------------------------------------------------------------
__global__ void __launch_bounds__(256)
final_kernel(const float* __restrict__ w2x,
             const float* __restrict__ w2n,
             const float* __restrict__ fcW,
             const float* __restrict__ fcb,
             float* __restrict__ out) {
    __shared__ float in_sh[16][512];
    __shared__ float sSq[16], sDot[16];
    int t  = threadIdx.x;
    int r0 = blockIdx.x * 16;

    {
        const float4* src = (const float4*)(g_scr + (size_t)r0 * 512);
        float4* dst = (float4*)&in_sh[0][0];
#pragma unroll
        for (int q = 0; q < 8; q++) dst[t + q * 256] = src[t + q * 256];
    }
    if (t < 16) { sSq[t] = 0.f; sDot[t] = 0.f; }
    __syncthreads();

    const int cp = t & 127;          // colpair -> cols 2cp, 2cp+1
    const int rh = t >> 7;           // row half -> rows rh*8 .. rh*8+7
    const int c0 = 2 * cp;
    const float* W0;
    int ioff;
    if (c0 < 128) { W0 = w2x + (size_t)c0 * 256;         ioff = 0;   }
    else          { W0 = w2n + (size_t)(c0 - 128) * 256; ioff = 256; }
    const float* W1 = W0 + 256;

    ull acc0[8], acc1[8];
#pragma unroll
    for (int r = 0; r < 8; r++) { acc0[r] = 0ull; acc1[r] = 0ull; }

    for (int c = 0; c < 256; c += 4) {
        ulonglong2 wv0 = *(const ulonglong2*)(W0 + c);
        ulonglong2 wv1 = *(const ulonglong2*)(W1 + c);
#pragma unroll
        for (int r = 0; r < 8; r++) {
            ulonglong2 x = *(const ulonglong2*)&in_sh[rh * 8 + r][ioff + c];
            FFMA2(acc0[r], x.x, wv0.x); FFMA2(acc0[r], x.y, wv0.y);
            FFMA2(acc1[r], x.x, wv1.x); FFMA2(acc1[r], x.y, wv1.y);
        }
    }

    float fw0 = fcW[c0], fw1 = fcW[c0 + 1];
#pragma unroll
    for (int r = 0; r < 8; r++) {
        int row = rh * 8 + r;
        float v0 = __uint_as_float((unsigned)acc0[r])
                 + __uint_as_float((unsigned)(acc0[r] >> 32));
        float v1 = __uint_as_float((unsigned)acc1[r])
                 + __uint_as_float((unsigned)(acc1[r] >> 32));
        float sq = v0 * v0 + v1 * v1;
        float dt = v0 * fw0 + v1 * fw1;
#pragma unroll
        for (int o = 16; o > 0; o >>= 1) {
            sq += __shfl_xor_sync(0xffffffffu, sq, o);
            dt += __shfl_xor_sync(0xffffffffu, dt, o);
        }
        if ((t & 31) == 0) { atomicAdd(&sSq[row], sq); atomicAdd(&sDot[row], dt); }
    }
    __syncthreads();
    if (t < 16) {
        float nrm = sqrtf(sSq[t]);
        out[r0 + t] = sDot[t] / fmaxf(nrm, 1e-12f) + fcb[0];
    }
}

// ---------------------------------------------------------------------------
extern "C" void kernel_launch(void* const* d_in, const int* in_sizes, int n_in,
                              void* d_out, int out_size) {
    const float* embedding = (const float*)d_in[0];
    const float* prep_W    = (const float*)d_in[1];
    const float* prep_b    = (const float*)d_in[2];
    const float* w1x       = (const float*)d_in[3];
    const float* w1n       = (const float*)d_in[4];
    const float* w2x       = (const float*)d_in[5];
    const float* w2n       = (const float*)d_in[6];
    const float* fcW       = (const float*)d_in[7];
    const float* fcb       = (const float*)d_in[8];
    const int*   ids       = (const int*)d_in[9];
    const int*   adj       = (const int*)d_in[10];
    const int*   perm1     = (const int*)d_in[11];
    const int*   perm2     = (const int*)d_in[12];
    const int n_nodes = in_sizes[0] / EMB - 1;

    prep_A<<<64, 128>>>(prep_W, w1x, w1n);
    prep_B<<<1, 128>>>(embedding, prep_W, prep_b, w1x, w1n, n_nodes);

    gather_kernel<<<NSAMP / 8, 256>>>(embedding, ids, adj, perm1, perm2);

    const int smem_c = SM_C_FLOATS * (int)sizeof(float);
    cudaFuncSetAttribute(compute_kernel, cudaFuncAttributeMaxDynamicSharedMemorySize, smem_c);
    compute_kernel<<<BATCH / 2, 256, smem_c>>>();

    final_kernel<<<BATCH / 16, 256>>>(w2x, w2n, fcW, fcb, (float*)d_out);
}